// round 3
// baseline (speedup 1.0000x reference)
#include <cuda_runtime.h>

// Input order (metadata): W1 b1 W2 b2 W3 b3 G1..G6 data_x func_val data_y step_size
// Output: [B, 388] float32 = [w_flat(193) | g_flat(193) | loss | improvement]

#define BDIM  128
#define WARPS 4
#define NSAMP 150
#define NITER 5            // ceil(150/32)

__constant__ float c_lr[6] = {0.001f, 0.01f, 0.05f, 0.1f, 0.5f, 1.0f};

__device__ float g_partials[16384];
__device__ float g_coef;

static __device__ __forceinline__ float clamp1e4(float v) {
    return fminf(fmaxf(v, -10000.0f), 10000.0f);
}

// Param flat layout (matches reference concat order):
//   W1  [0,40)    idx h*4+f
//   b1  [40,50)
//   W2  [50,150)  idx g*10+h
//   b2  [150,160)
//   W3  [160,190) idx o*10+g
//   b3  [190,193)

__global__ __launch_bounds__(BDIM) void k_mlp(
    const float* __restrict__ W1, const float* __restrict__ B1,
    const float* __restrict__ W2, const float* __restrict__ B2,
    const float* __restrict__ W3, const float* __restrict__ B3,
    const float* __restrict__ G1, const float* __restrict__ G2,
    const float* __restrict__ G3, const float* __restrict__ G4,
    const float* __restrict__ G5, const float* __restrict__ G6,
    const float* __restrict__ dx, const float* __restrict__ fv,
    const int*   __restrict__ dy, const int*   __restrict__ ss,
    float* __restrict__ out)
{
    __shared__ float4 sx[NSAMP];
    __shared__ int    sy[NSAMP];
    __shared__ float  ws_s[WARPS][193];
    __shared__ __align__(16) float srow[WARPS][388];
    __shared__ float  swsq[WARPS];

    const int tid  = threadIdx.x;
    const int lane = tid & 31;
    const int w    = tid >> 5;
    const int b    = blockIdx.x * WARPS + w;

    // Shared dataset (identical for every block; L2-hot)
    for (int i = tid; i < NSAMP; i += BDIM) {
        sx[i] = reinterpret_cast<const float4*>(dx)[i];
        sy[i] = dy[i];
    }
    __syncthreads();

    float* ws  = ws_s[w];
    float* row = srow[w];

    // ---- SGD update: w = p - lr*g; clipped copy into output row ----
    const float lr = c_lr[ss[b]];
#define UPD(P, G, OFF, CNT)                                               \
    for (int i = lane; i < CNT; i += 32) {                                \
        float v = P[(size_t)b * CNT + i] - lr * G[(size_t)b * CNT + i];   \
        ws[OFF + i] = v;                                                  \
        row[OFF + i] = clamp1e4(v);                                       \
    }
    UPD(W1, G1, 0, 40)
    UPD(B1, G2, 40, 10)
    UPD(W2, G3, 50, 100)
    UPD(B2, G4, 150, 10)
    UPD(W3, G5, 160, 30)
    UPD(B3, G6, 190, 3)
#undef UPD
    __syncwarp();

    // ---- forward + backward, lane = sample, grads accumulated in regs ----
    float acc[193];
#pragma unroll
    for (int i = 0; i < 193; ++i) acc[i] = 0.0f;
    float loss_sum = 0.0f;

#pragma unroll 1
    for (int it = 0; it < NITER; ++it) {
        const int  n      = it * 32 + lane;
        const bool active = (n < NSAMP);
        const int  nc     = active ? n : 0;
        const float4 xv   = sx[nc];
        const int  y      = sy[nc];
        const float wN    = active ? (1.0f / (float)NSAMP) : 0.0f;

        // layer 1
        float h1[10];
#pragma unroll
        for (int h = 0; h < 10; ++h) {
            float z = ws[40 + h];
            z = fmaf(ws[h * 4 + 0], xv.x, z);
            z = fmaf(ws[h * 4 + 1], xv.y, z);
            z = fmaf(ws[h * 4 + 2], xv.z, z);
            z = fmaf(ws[h * 4 + 3], xv.w, z);
            h1[h] = fmaxf(z, 0.0f);
        }
        // layer 2
        float h2[10];
#pragma unroll
        for (int g = 0; g < 10; ++g) {
            float z = ws[150 + g];
#pragma unroll
            for (int h = 0; h < 10; ++h) z = fmaf(ws[50 + g * 10 + h], h1[h], z);
            h2[g] = fmaxf(z, 0.0f);
        }
        // layer 3
        float l0 = ws[190], l1 = ws[191], l2 = ws[192];
#pragma unroll
        for (int g = 0; g < 10; ++g) {
            l0 = fmaf(ws[160 + g], h2[g], l0);
            l1 = fmaf(ws[170 + g], h2[g], l1);
            l2 = fmaf(ws[180 + g], h2[g], l2);
        }
        // softmax CE
        const float m  = fmaxf(l0, fmaxf(l1, l2));
        const float e0 = __expf(l0 - m), e1 = __expf(l1 - m), e2 = __expf(l2 - m);
        const float s  = e0 + e1 + e2;
        const float inv = __fdividef(1.0f, s);
        const float ly = (y == 0) ? l0 : ((y == 1) ? l1 : l2);
        loss_sum += active ? (m + __logf(s) - ly) : 0.0f;

        const float d0 = (e0 * inv - ((y == 0) ? 1.0f : 0.0f)) * wN;
        const float d1 = (e1 * inv - ((y == 1) ? 1.0f : 0.0f)) * wN;
        const float d2 = (e2 * inv - ((y == 2) ? 1.0f : 0.0f)) * wN;

        // layer 3 backward
        acc[190] += d0; acc[191] += d1; acc[192] += d2;
        float dh2[10];
#pragma unroll
        for (int g = 0; g < 10; ++g) {
            acc[160 + g] = fmaf(d0, h2[g], acc[160 + g]);
            acc[170 + g] = fmaf(d1, h2[g], acc[170 + g]);
            acc[180 + g] = fmaf(d2, h2[g], acc[180 + g]);
            float t = d0 * ws[160 + g];
            t = fmaf(d1, ws[170 + g], t);
            t = fmaf(d2, ws[180 + g], t);
            dh2[g] = (h2[g] > 0.0f) ? t : 0.0f;
        }
        // layer 2 backward
#pragma unroll
        for (int g = 0; g < 10; ++g) {
            acc[150 + g] += dh2[g];
#pragma unroll
            for (int h = 0; h < 10; ++h)
                acc[50 + g * 10 + h] = fmaf(dh2[g], h1[h], acc[50 + g * 10 + h]);
        }
        // layer 1 backward (dh1 streamed, one reg)
#pragma unroll
        for (int h = 0; h < 10; ++h) {
            float t = 0.0f;
#pragma unroll
            for (int g = 0; g < 10; ++g) t = fmaf(dh2[g], ws[50 + g * 10 + h], t);
            t = (h1[h] > 0.0f) ? t : 0.0f;
            acc[40 + h] += t;
            acc[h * 4 + 0] = fmaf(t, xv.x, acc[h * 4 + 0]);
            acc[h * 4 + 1] = fmaf(t, xv.y, acc[h * 4 + 1]);
            acc[h * 4 + 2] = fmaf(t, xv.z, acc[h * 4 + 2]);
            acc[h * 4 + 3] = fmaf(t, xv.w, acc[h * 4 + 3]);
        }
    }

    // ---- loss reduce ----
#pragma unroll
    for (int m2 = 16; m2; m2 >>= 1)
        loss_sum += __shfl_xor_sync(0xffffffffu, loss_sum, m2);
    const float loss_b = loss_sum * (1.0f / (float)NSAMP);

    // ---- grad reduce: exchange-halving; lane l ends with index grp*32+l ----
    float sumsq = 0.0f;
#pragma unroll
    for (int grp = 0; grp < 7; ++grp) {
        float r[32];
#pragma unroll
        for (int k = 0; k < 32; ++k) {
            const int idx = grp * 32 + k;
            r[k] = (idx < 193) ? acc[idx] : 0.0f;
        }
#pragma unroll
        for (int st = 0; st < 5; ++st) {
            const int half = 16 >> st;
            const bool up = (lane & half) != 0;
#pragma unroll
            for (int i = 0; i < 16; ++i) {
                if (i < half) {
                    const float a = r[i], bb = r[i + half];
                    const float keep = up ? bb : a;
                    const float send = up ? a : bb;
                    r[i] = keep + __shfl_xor_sync(0xffffffffu, send, half);
                }
            }
        }
        const int idx = grp * 32 + lane;
        if (idx < 193) {
            row[193 + idx] = r[0];
            sumsq += r[0] * r[0];
        }
    }
#pragma unroll
    for (int m2 = 16; m2; m2 >>= 1)
        sumsq += __shfl_xor_sync(0xffffffffu, sumsq, m2);

    if (lane == 0) {
        row[386] = loss_b;
        row[387] = clamp1e4(fv[b] - loss_b);
        swsq[w] = sumsq;
    }
    __syncwarp();

    // ---- vectorized row store: 388 floats = 97 float4 ----
    float4*       dst = reinterpret_cast<float4*>(out + (size_t)b * 388);
    const float4* src = reinterpret_cast<const float4*>(row);
#pragma unroll
    for (int i = lane; i < 97; i += 32) dst[i] = src[i];

    __syncthreads();
    if (tid == 0)
        g_partials[blockIdx.x] = swsq[0] + swsq[1] + swsq[2] + swsq[3];
}

__global__ void k_norm(int nparts) {
    __shared__ float sh[32];
    float s = 0.0f;
    for (int i = threadIdx.x; i < nparts; i += blockDim.x) s += g_partials[i];
#pragma unroll
    for (int m = 16; m; m >>= 1) s += __shfl_xor_sync(0xffffffffu, s, m);
    if ((threadIdx.x & 31) == 0) sh[threadIdx.x >> 5] = s;
    __syncthreads();
    if (threadIdx.x < 32) {
        float t = (threadIdx.x < (blockDim.x >> 5)) ? sh[threadIdx.x] : 0.0f;
#pragma unroll
        for (int m = 16; m; m >>= 1) t += __shfl_xor_sync(0xffffffffu, t, m);
        if (threadIdx.x == 0) {
            const float tn = sqrtf(t);
            g_coef = fminf(1.0f, 10.0f / (tn + 1e-6f));
        }
    }
}

__global__ void k_scale(float* __restrict__ out, int B) {
    const int idx = blockIdx.x * blockDim.x + threadIdx.x;
    const int total = B * 193;
    if (idx < total) {
        const int b = idx / 193;
        const int j = idx - b * 193;
        out[(size_t)b * 388 + 193 + j] *= g_coef;
    }
}

extern "C" void kernel_launch(void* const* d_in, const int* in_sizes, int n_in,
                              void* d_out, int out_size)
{
    const float* W1 = (const float*)d_in[0];
    const float* B1 = (const float*)d_in[1];
    const float* W2 = (const float*)d_in[2];
    const float* B2 = (const float*)d_in[3];
    const float* W3 = (const float*)d_in[4];
    const float* B3 = (const float*)d_in[5];
    const float* G1 = (const float*)d_in[6];
    const float* G2 = (const float*)d_in[7];
    const float* G3 = (const float*)d_in[8];
    const float* G4 = (const float*)d_in[9];
    const float* G5 = (const float*)d_in[10];
    const float* G6 = (const float*)d_in[11];
    const float* dx = (const float*)d_in[12];
    const float* fv = (const float*)d_in[13];
    const int*   dy = (const int*)d_in[14];
    const int*   ss = (const int*)d_in[15];
    float* out = (float*)d_out;

    const int B = in_sizes[13];          // func_val is [B]
    const int grid1 = B / WARPS;         // 8192 for B=32768

    k_mlp<<<grid1, BDIM>>>(W1, B1, W2, B2, W3, B3,
                           G1, G2, G3, G4, G5, G6,
                           dx, fv, dy, ss, out);
    k_norm<<<1, 1024>>>(grid1);
    const int total = B * 193;
    k_scale<<<(total + 255) / 256, 256>>>(out, B);
}

// round 5
// speedup vs baseline: 1.2176x; 1.2176x over previous
#include <cuda_runtime.h>

// Input order (metadata): W1 b1 W2 b2 W3 b3 G1..G6 data_x func_val data_y step_size
// Output: [B, 388] float32 = [w_flat(193) | g_flat(193) | loss | improvement]

#define BDIM  128
#define WARPS 4
#define NSAMP 150
#define NITER 5            // ceil(150/32)
#define SROWS 48
#define SSTR  36           // padded row stride (floats): 16B-aligned, bank-spread

// S row map (per warp):
//   [0,10)   t   (dh1)
//   [10,20)  dh2
//   [20,23)  d0..d2
//   [23,33)  h1
//   [33,43)  h2
//   [43,47)  x0..x3
//   47       ones

__constant__ float c_lr[6] = {0.001f, 0.01f, 0.05f, 0.1f, 0.5f, 1.0f};

__device__ float g_partials[16384];
__device__ float g_coef;

static __device__ __forceinline__ float clamp1e4(float v) {
    return fminf(fmaxf(v, -10000.0f), 10000.0f);
}

// Param flat layout (matches reference concat order):
//   W1 [0,40) h*4+f | b1 [40,50) | W2 [50,150) g*10+h | b2 [150,160)
//   W3 [160,190) o*10+g | b3 [190,193)

__global__ __launch_bounds__(BDIM) void k_mlp(
    const float* __restrict__ W1, const float* __restrict__ B1,
    const float* __restrict__ W2, const float* __restrict__ B2,
    const float* __restrict__ W3, const float* __restrict__ B3,
    const float* __restrict__ G1, const float* __restrict__ G2,
    const float* __restrict__ G3, const float* __restrict__ G4,
    const float* __restrict__ G5, const float* __restrict__ G6,
    const float* __restrict__ dx, const float* __restrict__ fv,
    const int*   __restrict__ dy, const int*   __restrict__ ss,
    float* __restrict__ out)
{
    __shared__ float4 sx[NSAMP];
    __shared__ int    sy[NSAMP];
    __shared__ float  ws_s[WARPS][193];
    __shared__ __align__(16) float S_s[WARPS][SROWS * SSTR];
    __shared__ float  swsq[WARPS];

    const int tid  = threadIdx.x;
    const int lane = tid & 31;
    const int w    = tid >> 5;
    const int b    = blockIdx.x * WARPS + w;

    // Shared dataset (identical for every block; L2-hot)
    for (int i = tid; i < NSAMP; i += BDIM) {
        sx[i] = reinterpret_cast<const float4*>(dx)[i];
        sy[i] = dy[i];
    }
    __syncthreads();

    float* ws = ws_s[w];
    float* S  = S_s[w];
    float* orow = out + (size_t)b * 388;

    // ---- SGD update: w = p - lr*g; clipped copy straight to output ----
    const float lr = c_lr[ss[b]];
#define UPD(P, G, OFF, CNT)                                               \
    for (int i = lane; i < CNT; i += 32) {                                \
        float v = P[(size_t)b * CNT + i] - lr * G[(size_t)b * CNT + i];   \
        ws[OFF + i] = v;                                                  \
        orow[OFF + i] = clamp1e4(v);                                      \
    }
    UPD(W1, G1, 0, 40)
    UPD(B1, G2, 40, 10)
    UPD(W2, G3, 50, 100)
    UPD(B2, G4, 150, 10)
    UPD(W3, G5, 160, 30)
    UPD(B3, G6, 190, 3)
#undef UPD

    // ones row for bias-gradient dot-products (constant for whole kernel)
    S[47 * SSTR + lane] = 1.0f;

    // ---- per-lane factor-row offsets for the 7 owned gradient entries ----
    int aOff[7], bOff[7];
#pragma unroll
    for (int g = 0; g < 7; ++g) {
        const int j = g * 32 + lane;
        int ar, br;
        if (j < 40)       { ar = j >> 2;              br = 43 + (j & 3); }
        else if (j < 50)  { ar = j - 40;              br = 47; }
        else if (j < 150) { int u = j - 50;  ar = 10 + u / 10; br = 23 + u % 10; }
        else if (j < 160) { ar = 10 + (j - 150);      br = 47; }
        else if (j < 190) { int u = j - 160; ar = 20 + u / 10; br = 33 + u % 10; }
        else if (j < 193) { ar = 20 + (j - 190);      br = 47; }
        else              { ar = 0;                   br = 0; }
        aOff[g] = ar * SSTR;
        bOff[g] = br * SSTR;
    }

    float accv[7];
#pragma unroll
    for (int g = 0; g < 7; ++g) accv[g] = 0.0f;
    float loss_sum = 0.0f;

#pragma unroll 1
    for (int it = 0; it < NITER; ++it) {
        const int  n      = it * 32 + lane;
        const bool active = (n < NSAMP);
        const int  nc     = active ? n : 0;
        const float4 xv   = sx[nc];
        const int  y      = sy[nc];
        const float wN    = active ? (1.0f / (float)NSAMP) : 0.0f;

        // layer 1
        float h1[10];
#pragma unroll
        for (int h = 0; h < 10; ++h) {
            float z = ws[40 + h];
            z = fmaf(ws[h * 4 + 0], xv.x, z);
            z = fmaf(ws[h * 4 + 1], xv.y, z);
            z = fmaf(ws[h * 4 + 2], xv.z, z);
            z = fmaf(ws[h * 4 + 3], xv.w, z);
            h1[h] = fmaxf(z, 0.0f);
        }
        // layer 2
        float h2[10];
#pragma unroll
        for (int g = 0; g < 10; ++g) {
            float z = ws[150 + g];
#pragma unroll
            for (int h = 0; h < 10; ++h) z = fmaf(ws[50 + g * 10 + h], h1[h], z);
            h2[g] = fmaxf(z, 0.0f);
        }
        // layer 3
        float l0 = ws[190], l1 = ws[191], l2 = ws[192];
#pragma unroll
        for (int g = 0; g < 10; ++g) {
            l0 = fmaf(ws[160 + g], h2[g], l0);
            l1 = fmaf(ws[170 + g], h2[g], l1);
            l2 = fmaf(ws[180 + g], h2[g], l2);
        }
        // softmax CE
        const float m  = fmaxf(l0, fmaxf(l1, l2));
        const float e0 = __expf(l0 - m), e1 = __expf(l1 - m), e2 = __expf(l2 - m);
        const float s  = e0 + e1 + e2;
        const float inv = __fdividef(1.0f, s);
        const float ly = (y == 0) ? l0 : ((y == 1) ? l1 : l2);
        loss_sum += active ? (m + __logf(s) - ly) : 0.0f;

        const float d0 = (e0 * inv - ((y == 0) ? 1.0f : 0.0f)) * wN;
        const float d1 = (e1 * inv - ((y == 1) ? 1.0f : 0.0f)) * wN;
        const float d2 = (e2 * inv - ((y == 2) ? 1.0f : 0.0f)) * wN;

        // dh2 = relu' * (W3^T d)
        float dh2[10];
#pragma unroll
        for (int g = 0; g < 10; ++g) {
            float t = d0 * ws[160 + g];
            t = fmaf(d1, ws[170 + g], t);
            t = fmaf(d2, ws[180 + g], t);
            dh2[g] = (h2[g] > 0.0f) ? t : 0.0f;
        }

        // ---- stage per-sample factor vectors into SMEM (column = lane) ----
        S[20 * SSTR + lane] = d0;
        S[21 * SSTR + lane] = d1;
        S[22 * SSTR + lane] = d2;
        S[43 * SSTR + lane] = xv.x;
        S[44 * SSTR + lane] = xv.y;
        S[45 * SSTR + lane] = xv.z;
        S[46 * SSTR + lane] = xv.w;
#pragma unroll
        for (int h = 0; h < 10; ++h) {
            S[(23 + h) * SSTR + lane] = h1[h];
            S[(33 + h) * SSTR + lane] = h2[h];
            S[(10 + h) * SSTR + lane] = dh2[h];
        }
        // t = relu' * (W2^T dh2), streamed straight to SMEM
#pragma unroll
        for (int h = 0; h < 10; ++h) {
            float t = 0.0f;
#pragma unroll
            for (int g = 0; g < 10; ++g) t = fmaf(dh2[g], ws[50 + g * 10 + h], t);
            t = (h1[h] > 0.0f) ? t : 0.0f;
            S[h * SSTR + lane] = t;
        }
        __syncwarp();

        // ---- accumulate owned gradient entries: dot over 32 samples ----
#pragma unroll
        for (int g = 0; g < 7; ++g) {
            const float4* A  = reinterpret_cast<const float4*>(S + aOff[g]);
            const float4* Bv = reinterpret_cast<const float4*>(S + bOff[g]);
            float sum = accv[g];
#pragma unroll
            for (int q = 0; q < 8; ++q) {
                const float4 a = A[q], c = Bv[q];
                sum = fmaf(a.x, c.x, sum);
                sum = fmaf(a.y, c.y, sum);
                sum = fmaf(a.z, c.z, sum);
                sum = fmaf(a.w, c.w, sum);
            }
            accv[g] = sum;
        }
        __syncwarp();
    }

    // ---- loss reduce ----
#pragma unroll
    for (int m2 = 16; m2; m2 >>= 1)
        loss_sum += __shfl_xor_sync(0xffffffffu, loss_sum, m2);
    const float loss_b = loss_sum * (1.0f / (float)NSAMP);

    // ---- store grads (unscaled) + per-lane sumsq ----
    float sumsq = 0.0f;
#pragma unroll
    for (int g = 0; g < 7; ++g) {
        const int j = g * 32 + lane;
        if (j < 193) {
            orow[193 + j] = accv[g];
            sumsq = fmaf(accv[g], accv[g], sumsq);
        }
    }
#pragma unroll
    for (int m2 = 16; m2; m2 >>= 1)
        sumsq += __shfl_xor_sync(0xffffffffu, sumsq, m2);

    if (lane == 0) {
        orow[386] = loss_b;
        orow[387] = clamp1e4(fv[b] - loss_b);
        swsq[w] = sumsq;
    }
    __syncthreads();
    if (tid == 0)
        g_partials[blockIdx.x] = swsq[0] + swsq[1] + swsq[2] + swsq[3];
}

__global__ void k_norm(int nparts) {
    __shared__ float sh[32];
    float s = 0.0f;
    for (int i = threadIdx.x; i < nparts; i += blockDim.x) s += g_partials[i];
#pragma unroll
    for (int m = 16; m; m >>= 1) s += __shfl_xor_sync(0xffffffffu, s, m);
    if ((threadIdx.x & 31) == 0) sh[threadIdx.x >> 5] = s;
    __syncthreads();
    if (threadIdx.x < 32) {
        float t = (threadIdx.x < (blockDim.x >> 5)) ? sh[threadIdx.x] : 0.0f;
#pragma unroll
        for (int m = 16; m; m >>= 1) t += __shfl_xor_sync(0xffffffffu, t, m);
        if (threadIdx.x == 0) {
            const float tn = sqrtf(t);
            g_coef = fminf(1.0f, 10.0f / (tn + 1e-6f));
        }
    }
}

__global__ void k_scale(float* __restrict__ out, int B) {
    const int idx = blockIdx.x * blockDim.x + threadIdx.x;
    const int total = B * 193;
    if (idx < total) {
        const int b = idx / 193;
        const int j = idx - b * 193;
        out[(size_t)b * 388 + 193 + j] *= g_coef;
    }
}

extern "C" void kernel_launch(void* const* d_in, const int* in_sizes, int n_in,
                              void* d_out, int out_size)
{
    const float* W1 = (const float*)d_in[0];
    const float* B1 = (const float*)d_in[1];
    const float* W2 = (const float*)d_in[2];
    const float* B2 = (const float*)d_in[3];
    const float* W3 = (const float*)d_in[4];
    const float* B3 = (const float*)d_in[5];
    const float* G1 = (const float*)d_in[6];
    const float* G2 = (const float*)d_in[7];
    const float* G3 = (const float*)d_in[8];
    const float* G4 = (const float*)d_in[9];
    const float* G5 = (const float*)d_in[10];
    const float* G6 = (const float*)d_in[11];
    const float* dx = (const float*)d_in[12];
    const float* fv = (const float*)d_in[13];
    const int*   dy = (const int*)d_in[14];
    const int*   ss = (const int*)d_in[15];
    float* out = (float*)d_out;

    const int B = in_sizes[13];          // func_val is [B]
    const int grid1 = B / WARPS;         // 8192 for B=32768

    k_mlp<<<grid1, BDIM>>>(W1, B1, W2, B2, W3, B3,
                           G1, G2, G3, G4, G5, G6,
                           dx, fv, dy, ss, out);
    k_norm<<<1, 1024>>>(grid1);
    const int total = B * 193;
    k_scale<<<(total + 255) / 256, 256>>>(out, B);
}

// round 11
// speedup vs baseline: 1.4491x; 1.1901x over previous
#include <cuda_runtime.h>

// Input order (metadata): W1 b1 W2 b2 W3 b3 G1..G6 data_x func_val data_y step_size
// Output: [B, 388] float32 = [w_flat(193) | g_flat(193) | loss | improvement]

#define BDIM  128
#define WARPS 4
#define NSAMP 150
#define NITER 3            // 64 samples/iter (2 per lane), 192 slots >= 150

__constant__ float c_lr[6] = {0.001f, 0.01f, 0.05f, 0.1f, 0.5f, 1.0f};

__device__ float g_partials[16384];
__device__ float g_coef;

static __device__ __forceinline__ float clamp1e4(float v) {
    return fminf(fmaxf(v, -10000.0f), 10000.0f);
}

// Param flat layout (matches reference concat order):
//   W1 [0,40) h*4+f | b1 [40,50) | W2 [50,150) g*10+h | b2 [150,160)
//   W3 [160,190) o*10+g | b3 [190,193)

// Factor selectors; j is always a compile-time constant (fully unrolled callers)
static __device__ __forceinline__ float fA(const float (&t)[10], const float (&dh2)[10],
                                           const float (&d)[3], int j) {
    if (j < 40)  return t[j >> 2];
    if (j < 50)  return t[j - 40];
    if (j < 150) return dh2[(j - 50) / 10];
    if (j < 160) return dh2[j - 150];
    if (j < 190) return d[(j - 160) / 10];
    if (j < 193) return d[j - 190];
    return 0.0f;
}
static __device__ __forceinline__ float fB(const float (&h1)[10], const float (&h2)[10],
                                           const float4& x, int j) {
    if (j < 40) {
        const int f = j & 3;
        return f == 0 ? x.x : (f == 1 ? x.y : (f == 2 ? x.z : x.w));
    }
    if (j < 50)  return 1.0f;
    if (j < 150) return h1[(j - 50) % 10];
    if (j < 160) return 1.0f;
    if (j < 190) return h2[(j - 160) % 10];
    return 1.0f;
}

__global__ __launch_bounds__(BDIM) void k_mlp(
    const float* __restrict__ W1, const float* __restrict__ B1,
    const float* __restrict__ W2, const float* __restrict__ B2,
    const float* __restrict__ W3, const float* __restrict__ B3,
    const float* __restrict__ G1, const float* __restrict__ G2,
    const float* __restrict__ G3, const float* __restrict__ G4,
    const float* __restrict__ G5, const float* __restrict__ G6,
    const float* __restrict__ dx, const float* __restrict__ fv,
    const int*   __restrict__ dy, const int*   __restrict__ ss,
    float* __restrict__ out)
{
    __shared__ float4 sx[NSAMP];
    __shared__ int    sy[NSAMP];
    __shared__ float  ws_s[WARPS][193];
    __shared__ float  swsq[WARPS];

    const int tid  = threadIdx.x;
    const int lane = tid & 31;
    const int w    = tid >> 5;
    const int b    = blockIdx.x * WARPS + w;

    for (int i = tid; i < NSAMP; i += BDIM) {
        sx[i] = reinterpret_cast<const float4*>(dx)[i];
        sy[i] = dy[i];
    }
    __syncthreads();

    float* ws   = ws_s[w];
    float* orow = out + (size_t)b * 388;

    // ---- SGD update: w = p - lr*g; clipped copy straight to output ----
    const float lr = c_lr[ss[b]];
#define UPD(P, G, OFF, CNT)                                               \
    for (int i = lane; i < CNT; i += 32) {                                \
        float v = P[(size_t)b * CNT + i] - lr * G[(size_t)b * CNT + i];   \
        ws[OFF + i] = v;                                                  \
        orow[OFF + i] = clamp1e4(v);                                      \
    }
    UPD(W1, G1, 0, 40)
    UPD(B1, G2, 40, 10)
    UPD(W2, G3, 50, 100)
    UPD(B2, G4, 150, 10)
    UPD(W3, G5, 160, 30)
    UPD(B3, G6, 190, 3)
#undef UPD
    __syncwarp();

    float acc[7];
#pragma unroll
    for (int g = 0; g < 7; ++g) acc[g] = 0.0f;
    float loss_sum = 0.0f;

#pragma unroll 1
    for (int it = 0; it < NITER; ++it) {
        const int nA = it * 64 + lane;
        const int nB = nA + 32;
        const bool actA = (nA < NSAMP), actB = (nB < NSAMP);
        const float4 xa = sx[actA ? nA : 0];
        const float4 xb = sx[actB ? nB : 0];
        const int ya = sy[actA ? nA : 0];
        const int yb = sy[actB ? nB : 0];
        const float wNa = actA ? (1.0f / (float)NSAMP) : 0.0f;
        const float wNb = actB ? (1.0f / (float)NSAMP) : 0.0f;

        // ---- layer 1 (weights loaded once, feed both samples) ----
        float h1a[10], h1b[10];
#pragma unroll
        for (int h = 0; h < 10; ++h) {
            float za = ws[40 + h], zb = za;
            { const float wv = ws[h * 4 + 0]; za = fmaf(wv, xa.x, za); zb = fmaf(wv, xb.x, zb); }
            { const float wv = ws[h * 4 + 1]; za = fmaf(wv, xa.y, za); zb = fmaf(wv, xb.y, zb); }
            { const float wv = ws[h * 4 + 2]; za = fmaf(wv, xa.z, za); zb = fmaf(wv, xb.z, zb); }
            { const float wv = ws[h * 4 + 3]; za = fmaf(wv, xa.w, za); zb = fmaf(wv, xb.w, zb); }
            h1a[h] = fmaxf(za, 0.0f); h1b[h] = fmaxf(zb, 0.0f);
        }
        // ---- layer 2 ----
        float h2a[10], h2b[10];
#pragma unroll
        for (int g = 0; g < 10; ++g) {
            float za = ws[150 + g], zb = za;
#pragma unroll
            for (int h = 0; h < 10; ++h) {
                const float wv = ws[50 + g * 10 + h];
                za = fmaf(wv, h1a[h], za); zb = fmaf(wv, h1b[h], zb);
            }
            h2a[g] = fmaxf(za, 0.0f); h2b[g] = fmaxf(zb, 0.0f);
        }
        // ---- layer 3 ----
        float l0a = ws[190], l1a = ws[191], l2a = ws[192];
        float l0b = l0a, l1b = l1a, l2b = l2a;
#pragma unroll
        for (int g = 0; g < 10; ++g) {
            const float w0 = ws[160 + g], w1 = ws[170 + g], w2 = ws[180 + g];
            l0a = fmaf(w0, h2a[g], l0a); l0b = fmaf(w0, h2b[g], l0b);
            l1a = fmaf(w1, h2a[g], l1a); l1b = fmaf(w1, h2b[g], l1b);
            l2a = fmaf(w2, h2a[g], l2a); l2b = fmaf(w2, h2b[g], l2b);
        }
        // ---- softmax CE, both samples ----
        float da[3], db[3];
        {
            const float m  = fmaxf(l0a, fmaxf(l1a, l2a));
            const float e0 = __expf(l0a - m), e1 = __expf(l1a - m), e2 = __expf(l2a - m);
            const float s  = e0 + e1 + e2;
            const float inv = __fdividef(1.0f, s);
            const float ly = (ya == 0) ? l0a : ((ya == 1) ? l1a : l2a);
            loss_sum += actA ? (m + __logf(s) - ly) : 0.0f;
            da[0] = (e0 * inv - ((ya == 0) ? 1.0f : 0.0f)) * wNa;
            da[1] = (e1 * inv - ((ya == 1) ? 1.0f : 0.0f)) * wNa;
            da[2] = (e2 * inv - ((ya == 2) ? 1.0f : 0.0f)) * wNa;
        }
        {
            const float m  = fmaxf(l0b, fmaxf(l1b, l2b));
            const float e0 = __expf(l0b - m), e1 = __expf(l1b - m), e2 = __expf(l2b - m);
            const float s  = e0 + e1 + e2;
            const float inv = __fdividef(1.0f, s);
            const float ly = (yb == 0) ? l0b : ((yb == 1) ? l1b : l2b);
            loss_sum += actB ? (m + __logf(s) - ly) : 0.0f;
            db[0] = (e0 * inv - ((yb == 0) ? 1.0f : 0.0f)) * wNb;
            db[1] = (e1 * inv - ((yb == 1) ? 1.0f : 0.0f)) * wNb;
            db[2] = (e2 * inv - ((yb == 2) ? 1.0f : 0.0f)) * wNb;
        }
        // ---- dh2 = relu' * (W3^T d) ----
        float dh2a[10], dh2b[10];
#pragma unroll
        for (int g = 0; g < 10; ++g) {
            const float w0 = ws[160 + g], w1 = ws[170 + g], w2 = ws[180 + g];
            float ta = da[0] * w0; ta = fmaf(da[1], w1, ta); ta = fmaf(da[2], w2, ta);
            float tb = db[0] * w0; tb = fmaf(db[1], w1, tb); tb = fmaf(db[2], w2, tb);
            dh2a[g] = (h2a[g] > 0.0f) ? ta : 0.0f;
            dh2b[g] = (h2b[g] > 0.0f) ? tb : 0.0f;
        }
        // ---- t = relu' * (W2^T dh2) ----
        float t_a[10], t_b[10];
#pragma unroll
        for (int h = 0; h < 10; ++h) {
            float ta = 0.0f, tb = 0.0f;
#pragma unroll
            for (int g = 0; g < 10; ++g) {
                const float wv = ws[50 + g * 10 + h];
                ta = fmaf(dh2a[g], wv, ta); tb = fmaf(dh2b[g], wv, tb);
            }
            t_a[h] = (h1a[h] > 0.0f) ? ta : 0.0f;
            t_b[h] = (h1b[h] > 0.0f) ? tb : 0.0f;
        }

        // ---- per-iter gradient reduction: register products + butterfly ----
#pragma unroll
        for (int grp = 0; grp < 7; ++grp) {
            float r[32];
#pragma unroll
            for (int k = 0; k < 32; ++k) {
                const int j = grp * 32 + k;
                const float pa = fA(t_a, dh2a, da, j) * fB(h1a, h2a, xa, j);
                r[k] = fmaf(fA(t_b, dh2b, db, j), fB(h1b, h2b, xb, j), pa);
            }
#pragma unroll
            for (int st = 0; st < 5; ++st) {
                const int half = 16 >> st;
                const bool up = (lane & half) != 0;
#pragma unroll
                for (int i = 0; i < 16; ++i) {
                    if (i < half) {
                        const float a2 = r[i], b2 = r[i + half];
                        const float keep = up ? b2 : a2;
                        const float send = up ? a2 : b2;
                        r[i] = keep + __shfl_xor_sync(0xffffffffu, send, half);
                    }
                }
            }
            acc[grp] += r[0];
        }
    }

    // ---- loss reduce ----
#pragma unroll
    for (int m2 = 16; m2; m2 >>= 1)
        loss_sum += __shfl_xor_sync(0xffffffffu, loss_sum, m2);
    const float loss_b = loss_sum * (1.0f / (float)NSAMP);

    // ---- store grads (unscaled) + per-lane sumsq ----
    float sumsq = 0.0f;
#pragma unroll
    for (int g = 0; g < 7; ++g) {
        const int j = g * 32 + lane;
        if (j < 193) {
            orow[193 + j] = acc[g];
            sumsq = fmaf(acc[g], acc[g], sumsq);
        }
    }
#pragma unroll
    for (int m2 = 16; m2; m2 >>= 1)
        sumsq += __shfl_xor_sync(0xffffffffu, sumsq, m2);

    if (lane == 0) {
        orow[386] = loss_b;
        orow[387] = clamp1e4(fv[b] - loss_b);
        swsq[w] = sumsq;
    }
    __syncthreads();
    if (tid == 0)
        g_partials[blockIdx.x] = swsq[0] + swsq[1] + swsq[2] + swsq[3];
}

__global__ void k_norm(int nparts) {
    __shared__ float sh[32];
    float s = 0.0f;
    for (int i = threadIdx.x; i < nparts; i += blockDim.x) s += g_partials[i];
#pragma unroll
    for (int m = 16; m; m >>= 1) s += __shfl_xor_sync(0xffffffffu, s, m);
    if ((threadIdx.x & 31) == 0) sh[threadIdx.x >> 5] = s;
    __syncthreads();
    if (threadIdx.x < 32) {
        float t = (threadIdx.x < (blockDim.x >> 5)) ? sh[threadIdx.x] : 0.0f;
#pragma unroll
        for (int m = 16; m; m >>= 1) t += __shfl_xor_sync(0xffffffffu, t, m);
        if (threadIdx.x == 0) {
            const float tn = sqrtf(t);
            g_coef = fminf(1.0f, 10.0f / (tn + 1e-6f));
        }
    }
}

__global__ void k_scale(float* __restrict__ out, int B) {
    const int idx = blockIdx.x * blockDim.x + threadIdx.x;
    const int total = B * 193;
    if (idx < total) {
        const int b = idx / 193;
        const int j = idx - b * 193;
        out[(size_t)b * 388 + 193 + j] *= g_coef;
    }
}

extern "C" void kernel_launch(void* const* d_in, const int* in_sizes, int n_in,
                              void* d_out, int out_size)
{
    const float* W1 = (const float*)d_in[0];
    const float* B1 = (const float*)d_in[1];
    const float* W2 = (const float*)d_in[2];
    const float* B2 = (const float*)d_in[3];
    const float* W3 = (const float*)d_in[4];
    const float* B3 = (const float*)d_in[5];
    const float* G1 = (const float*)d_in[6];
    const float* G2 = (const float*)d_in[7];
    const float* G3 = (const float*)d_in[8];
    const float* G4 = (const float*)d_in[9];
    const float* G5 = (const float*)d_in[10];
    const float* G6 = (const float*)d_in[11];
    const float* dx = (const float*)d_in[12];
    const float* fv = (const float*)d_in[13];
    const int*   dy = (const int*)d_in[14];
    const int*   ss = (const int*)d_in[15];
    float* out = (float*)d_out;

    const int B = in_sizes[13];          // func_val is [B]
    const int grid1 = B / WARPS;         // 8192 for B=32768

    k_mlp<<<grid1, BDIM>>>(W1, B1, W2, B2, W3, B3,
                           G1, G2, G3, G4, G5, G6,
                           dx, fv, dy, ss, out);
    k_norm<<<1, 1024>>>(grid1);
    const int total = B * 193;
    k_scale<<<(total + 255) / 256, 256>>>(out, B);
}